// round 5
// baseline (speedup 1.0000x reference)
#include <cuda_runtime.h>
#include <cuda_bf16.h>
#include <stdint.h>
#include <math.h>

#define B_DIM 8
#define C_DIM 256
#define H_DIM 128
#define W_DIM 128
#define HW    (H_DIM * W_DIM)
#define NTOK  (B_DIM * HW)
#define QK_SCALE 0.0625f

// q/k/v bf16 hi/lo split, [token][channel]
__device__ __nv_bfloat16 g_qhi[NTOK * C_DIM];
__device__ __nv_bfloat16 g_qlo[NTOK * C_DIM];
__device__ __nv_bfloat16 g_khi[NTOK * C_DIM];
__device__ __nv_bfloat16 g_klo[NTOK * C_DIM];
__device__ __nv_bfloat16 g_vhi[NTOK * C_DIM];
__device__ __nv_bfloat16 g_vlo[NTOK * C_DIM];
// Weights split: [mat][o][c]
__device__ __nv_bfloat16 g_whi[3 * C_DIM * C_DIM];
__device__ __nv_bfloat16 g_wlo[3 * C_DIM * C_DIM];

__device__ __forceinline__ uint32_t smem_u32(const void* p) {
    uint32_t a;
    asm("{ .reg .u64 t; cvta.to.shared.u64 t, %1; cvt.u32.u64 %0, t; }" : "=r"(a) : "l"(p));
    return a;
}
__device__ __forceinline__ void cp16(uint32_t dst, const void* src) {
    asm volatile("cp.async.cg.shared.global [%0], [%1], 16;" :: "r"(dst), "l"(src));
}
__device__ __forceinline__ void cp_commit() { asm volatile("cp.async.commit_group;" ::: "memory"); }
__device__ __forceinline__ void cp_wait1()  { asm volatile("cp.async.wait_group 1;" ::: "memory"); }
__device__ __forceinline__ void cp_wait0()  { asm volatile("cp.async.wait_group 0;" ::: "memory"); }

__device__ __forceinline__ void ldm_x4(uint32_t& r0, uint32_t& r1, uint32_t& r2, uint32_t& r3, uint32_t addr) {
    asm volatile("ldmatrix.sync.aligned.m8n8.x4.shared.b16 {%0,%1,%2,%3}, [%4];"
                 : "=r"(r0), "=r"(r1), "=r"(r2), "=r"(r3) : "r"(addr));
}
__device__ __forceinline__ void ldm_x4_t(uint32_t& r0, uint32_t& r1, uint32_t& r2, uint32_t& r3, uint32_t addr) {
    asm volatile("ldmatrix.sync.aligned.m8n8.x4.trans.shared.b16 {%0,%1,%2,%3}, [%4];"
                 : "=r"(r0), "=r"(r1), "=r"(r2), "=r"(r3) : "r"(addr));
}
__device__ __forceinline__ void mma16816(float* c, const uint32_t* a, uint32_t b0, uint32_t b1) {
    asm volatile("mma.sync.aligned.m16n8k16.row.col.f32.bf16.bf16.f32 "
                 "{%0,%1,%2,%3},{%4,%5,%6,%7},{%8,%9},{%0,%1,%2,%3};"
                 : "+f"(c[0]), "+f"(c[1]), "+f"(c[2]), "+f"(c[3])
                 : "r"(a[0]), "r"(a[1]), "r"(a[2]), "r"(a[3]), "r"(b0), "r"(b1));
}
__device__ __forceinline__ uint32_t pk_hi(float x, float y) {
    __nv_bfloat162 t = __floats2bfloat162_rn(x, y);
    return *(uint32_t*)&t;
}
__device__ __forceinline__ uint32_t pk_lo(float x, float y) {
    float xh = __bfloat162float(__float2bfloat16(x));
    float yh = __bfloat162float(__float2bfloat16(y));
    __nv_bfloat162 t = __floats2bfloat162_rn(x - xh, y - yh);
    return *(uint32_t*)&t;
}

__global__ __launch_bounds__(256)
void wconvert(const float* __restrict__ wq, const float* __restrict__ wk,
              const float* __restrict__ wv)
{
    int idx = blockIdx.x * 256 + threadIdx.x;
    int mat = idx >> 16, r = idx & 65535;
    const float* src = (mat == 0) ? wq : (mat == 1) ? wk : wv;
    float v = src[r];
    __nv_bfloat16 hi = __float2bfloat16(v);
    g_whi[idx] = hi;
    g_wlo[idx] = __float2bfloat16(v - __bfloat162float(hi));
}

// ===========================================================================
// Fused QKV: grid (6,1024), x = mat*2+half, y = scanline.
// CTA: 128 tok x 128 out. X hi/lo tiles [tok][256c] (512B rows, xor-swizzled)
// built once in smem from raw a; W streamed double-buffered. 3-pass split.
// ===========================================================================
#define QKV_SMEM 163840   // XHI 0, XLO 65536, B stages 131072 + s*16384

__global__ __launch_bounds__(256)
void qkv_mma(const float* __restrict__ a,
             const float* __restrict__ bq, const float* __restrict__ bk,
             const float* __restrict__ bv)
{
    extern __shared__ char smem[];
    const uint32_t sb = smem_u32(smem);
    const int tid = threadIdx.x, lane = tid & 31, wid = tid >> 5;
    const int wm0 = (wid & 3) * 32, wn0 = (wid >> 2) * 64;
    const int mat = blockIdx.x >> 1, half = blockIdx.x & 1;
    const int sline = blockIdx.y, b = sline >> 7, h = sline & 127;

    // conversion prologue: lanes vary channel-pair at fixed row -> conflict-free
    const float* ab = a + (size_t)b * C_DIM * HW + (size_t)h * W_DIM;
    #pragma unroll
    for (int it = 0; it < 16; ++it) {
        int idx = it * 256 + tid;          // 4096 items
        int c2 = idx & 127;                // channel pair
        int w4 = idx >> 7;                 // 0..31
        const float* p0 = ab + (size_t)(2 * c2) * HW + w4 * 4;
        float4 v0 = *(const float4*)p0;
        float4 v1 = *(const float4*)(p0 + HW);
        float xs[4] = {v0.x, v0.y, v0.z, v0.w};
        float ys[4] = {v1.x, v1.y, v1.z, v1.w};
        int c16 = c2 >> 2, bo = (c2 & 3) * 4;
        #pragma unroll
        for (int u = 0; u < 4; ++u) {
            int row = w4 * 4 + u;
            uint32_t off = row * 512 + ((c16 ^ (row & 7)) << 4) + bo;
            *(uint32_t*)(smem + off)         = pk_hi(xs[u], ys[u]);
            *(uint32_t*)(smem + 65536 + off) = pk_lo(xs[u], ys[u]);
        }
    }
    __syncthreads();

    float acc[2][8][4];
    #pragma unroll
    for (int mt = 0; mt < 2; ++mt)
        #pragma unroll
        for (int n8 = 0; n8 < 8; ++n8)
            #pragma unroll
            for (int e = 0; e < 4; ++e) acc[mt][n8][e] = 0.0f;

    auto loadB = [&](int stg, int j) {
        int wsel = j >> 2, kc = j & 3;
        const __nv_bfloat16* wb = (wsel ? g_wlo : g_whi)
            + mat * 65536 + (half * 128) * 256 + kc * 64;
        uint32_t st = sb + 131072 + stg * 16384;
        #pragma unroll
        for (int it = 0; it < 4; ++it) {
            int id = it * 256 + tid;
            int row = id >> 3, c16 = id & 7;
            cp16(st + row * 128 + ((c16 ^ (row & 7)) << 4), wb + row * 256 + c16 * 8);
        }
    };

    loadB(0, 0); cp_commit();
    for (int j = 0; j < 8; ++j) {
        if (j < 7) { loadB((j + 1) & 1, j + 1); cp_commit(); cp_wait1(); }
        else cp_wait0();
        __syncthreads();
        const uint32_t Bb = sb + 131072 + (j & 1) * 16384;
        const int wsel = j >> 2, kc = j & 3;
        #pragma unroll
        for (int ks = 0; ks < 4; ++ks) {
            uint32_t ah[2][4], al[2][4];
            const int c16 = kc * 8 + ks * 2 + (lane >> 4);
            #pragma unroll
            for (int mt = 0; mt < 2; ++mt) {
                int arow = wm0 + mt * 16 + (lane & 15);
                uint32_t aoff = arow * 512 + ((c16 ^ (arow & 7)) << 4);
                ldm_x4(ah[mt][0], ah[mt][1], ah[mt][2], ah[mt][3], sb + aoff);
                if (wsel == 0)
                    ldm_x4(al[mt][0], al[mt][1], al[mt][2], al[mt][3], sb + 65536 + aoff);
            }
            #pragma unroll
            for (int ng = 0; ng < 4; ++ng) {
                int brow = wn0 + ng * 16 + (lane & 15);
                int bc = ks * 2 + (lane >> 4);
                uint32_t boff = brow * 128 + ((bc ^ (brow & 7)) << 4);
                uint32_t b0, b1, b2, b3;
                ldm_x4(b0, b1, b2, b3, Bb + boff);
                #pragma unroll
                for (int mt = 0; mt < 2; ++mt) {
                    mma16816(acc[mt][2 * ng],     ah[mt], b0, b2);
                    mma16816(acc[mt][2 * ng + 1], ah[mt], b1, b3);
                    if (wsel == 0) {
                        mma16816(acc[mt][2 * ng],     al[mt], b0, b2);
                        mma16816(acc[mt][2 * ng + 1], al[mt], b1, b3);
                    }
                }
            }
        }
        __syncthreads();
    }

    const float* bias = (mat == 0) ? bq : (mat == 1) ? bk : bv;
    const float scale = (mat == 0) ? QK_SCALE : 1.0f;
    __nv_bfloat16* dhi = (mat == 0) ? g_qhi : (mat == 1) ? g_khi : g_vhi;
    __nv_bfloat16* dlo = (mat == 0) ? g_qlo : (mat == 1) ? g_klo : g_vlo;
    const int g = lane >> 2, t4 = lane & 3;
    #pragma unroll
    for (int mt = 0; mt < 2; ++mt) {
        size_t r0 = (size_t)sline * 128 + wm0 + mt * 16 + g, r1 = r0 + 8;
        #pragma unroll
        for (int n8 = 0; n8 < 8; ++n8) {
            int o = half * 128 + wn0 + n8 * 8 + t4 * 2;
            float b0v = bias[o], b1v = bias[o + 1];
            float v00 = (acc[mt][n8][0] + b0v) * scale;
            float v01 = (acc[mt][n8][1] + b1v) * scale;
            float v10 = (acc[mt][n8][2] + b0v) * scale;
            float v11 = (acc[mt][n8][3] + b1v) * scale;
            *(uint32_t*)(dhi + r0 * 256 + o) = pk_hi(v00, v01);
            *(uint32_t*)(dlo + r0 * 256 + o) = pk_lo(v00, v01);
            *(uint32_t*)(dhi + r1 * 256 + o) = pk_hi(v10, v11);
            *(uint32_t*)(dlo + r1 * 256 + o) = pk_lo(v10, v11);
        }
    }
}

// ===========================================================================
// HMMA attention: one CTA per scanline, 8 warps x 16 S-rows.
// ===========================================================================
#define ATTN_SMEM 164864  // QK stages 2x64KB; V stages 2x32KB overlay; Os @131072

__global__ __launch_bounds__(256)
void attn_mma(const float* __restrict__ a, const float* __restrict__ Wp,
              float* __restrict__ out)
{
    extern __shared__ char smem[];
    const uint32_t sb = smem_u32(smem);
    float* Os = (float*)(smem + 131072);   // [128][66]
    const int tid = threadIdx.x, lane = tid & 31, wid = tid >> 5;
    const int m0 = wid * 16;
    const int bh = blockIdx.x, b = bh >> 7, h = bh & 127;
    const size_t tokbase = (size_t)bh * 128;

    auto loadQK = [&](int stg, int kc) {
        uint32_t st = sb + stg * 65536;
        const size_t scol = tokbase * 256 + kc * 64;
        #pragma unroll
        for (int it = 0; it < 4; ++it) {
            int id = it * 256 + tid;
            int row = id >> 3, c16 = id & 7;
            uint32_t doff = row * 128 + ((c16 ^ (row & 7)) << 4);
            size_t soff = scol + (size_t)row * 256 + c16 * 8;
            cp16(st + 0     + doff, g_qhi + soff);
            cp16(st + 16384 + doff, g_qlo + soff);
            cp16(st + 32768 + doff, g_khi + soff);
            cp16(st + 49152 + doff, g_klo + soff);
        }
    };
    auto loadV = [&](int stg, int cc) {
        uint32_t st = sb + stg * 32768;
        const size_t scol = tokbase * 256 + cc * 64;
        #pragma unroll
        for (int it = 0; it < 4; ++it) {
            int id = it * 256 + tid;
            int row = id >> 3, c16 = id & 7;
            uint32_t doff = row * 128 + ((c16 ^ (row & 7)) << 4);
            size_t soff = scol + (size_t)row * 256 + c16 * 8;
            cp16(st + 0     + doff, g_vhi + soff);
            cp16(st + 16384 + doff, g_vlo + soff);
        }
    };

    float sacc[16][4];
    #pragma unroll
    for (int j = 0; j < 16; ++j)
        #pragma unroll
        for (int e = 0; e < 4; ++e) sacc[j][e] = 0.0f;

    loadQK(0, 0); cp_commit();
    for (int kc = 0; kc < 4; ++kc) {
        if (kc < 3) { loadQK((kc + 1) & 1, kc + 1); cp_commit(); cp_wait1(); }
        else cp_wait0();
        __syncthreads();
        const uint32_t st = sb + (kc & 1) * 65536;
        #pragma unroll
        for (int ks = 0; ks < 4; ++ks) {
            uint32_t ah[4], al[4];
            const int c16 = ks * 2 + (lane >> 4);
            int arow = m0 + (lane & 15);
            uint32_t aoff = arow * 128 + ((c16 ^ (arow & 7)) << 4);
            ldm_x4(ah[0], ah[1], ah[2], ah[3], st + aoff);
            ldm_x4(al[0], al[1], al[2], al[3], st + 16384 + aoff);
            #pragma unroll
            for (int bn = 0; bn < 8; ++bn) {
                int brow = bn * 16 + (lane & 15);
                uint32_t boff = brow * 128 + ((c16 ^ (brow & 7)) << 4);
                uint32_t b0, b1, b2, b3;
                ldm_x4(b0, b1, b2, b3, st + 32768 + boff);
                mma16816(sacc[2 * bn],     ah, b0, b2);
                mma16816(sacc[2 * bn + 1], ah, b1, b3);
                mma16816(sacc[2 * bn],     al, b0, b2);
                mma16816(sacc[2 * bn + 1], al, b1, b3);
                ldm_x4(b0, b1, b2, b3, st + 49152 + boff);
                mma16816(sacc[2 * bn],     ah, b0, b2);
                mma16816(sacc[2 * bn + 1], ah, b1, b3);
            }
        }
        __syncthreads();
    }
    loadV(0, 0); cp_commit();

    // softmax in accumulator layout: rows r0 = m0+(lane>>2), r1 = r0+8
    float mx0 = -1e30f, mx1 = -1e30f;
    #pragma unroll
    for (int j = 0; j < 16; ++j) {
        mx0 = fmaxf(mx0, fmaxf(sacc[j][0], sacc[j][1]));
        mx1 = fmaxf(mx1, fmaxf(sacc[j][2], sacc[j][3]));
    }
    mx0 = fmaxf(mx0, __shfl_xor_sync(~0u, mx0, 1));
    mx0 = fmaxf(mx0, __shfl_xor_sync(~0u, mx0, 2));
    mx1 = fmaxf(mx1, __shfl_xor_sync(~0u, mx1, 1));
    mx1 = fmaxf(mx1, __shfl_xor_sync(~0u, mx1, 2));
    float sum0 = 0.0f, sum1 = 0.0f;
    #pragma unroll
    for (int j = 0; j < 16; ++j) {
        sacc[j][0] = __expf(sacc[j][0] - mx0); sum0 += sacc[j][0];
        sacc[j][1] = __expf(sacc[j][1] - mx0); sum0 += sacc[j][1];
        sacc[j][2] = __expf(sacc[j][2] - mx1); sum1 += sacc[j][2];
        sacc[j][3] = __expf(sacc[j][3] - mx1); sum1 += sacc[j][3];
    }
    sum0 += __shfl_xor_sync(~0u, sum0, 1);
    sum0 += __shfl_xor_sync(~0u, sum0, 2);
    sum1 += __shfl_xor_sync(~0u, sum1, 1);
    sum1 += __shfl_xor_sync(~0u, sum1, 2);
    const float inv0 = 1.0f / sum0, inv1 = 1.0f / sum1;

    uint32_t phi[8][4], plo[8][4];
    #pragma unroll
    for (int kt = 0; kt < 8; ++kt) {
        int j0 = 2 * kt, j1 = 2 * kt + 1;
        float v00 = sacc[j0][0] * inv0, v01 = sacc[j0][1] * inv0;
        float v02 = sacc[j0][2] * inv1, v03 = sacc[j0][3] * inv1;
        float v10 = sacc[j1][0] * inv0, v11 = sacc[j1][1] * inv0;
        float v12 = sacc[j1][2] * inv1, v13 = sacc[j1][3] * inv1;
        phi[kt][0] = pk_hi(v00, v01); plo[kt][0] = pk_lo(v00, v01);
        phi[kt][1] = pk_hi(v02, v03); plo[kt][1] = pk_lo(v02, v03);
        phi[kt][2] = pk_hi(v10, v11); plo[kt][2] = pk_lo(v10, v11);
        phi[kt][3] = pk_hi(v12, v13); plo[kt][3] = pk_lo(v12, v13);
    }

    const float wpv = Wp[0];
    const int g = lane >> 2, t4 = lane & 3;

    for (int cc = 0; cc < 4; ++cc) {
        if (cc < 3) { loadV((cc + 1) & 1, cc + 1); cp_commit(); cp_wait1(); }
        else cp_wait0();
        __syncthreads();
        const uint32_t vs = sb + (cc & 1) * 32768;
        float oacc[8][4];
        #pragma unroll
        for (int j = 0; j < 8; ++j)
            #pragma unroll
            for (int e = 0; e < 4; ++e) oacc[j][e] = 0.0f;

        #pragma unroll
        for (int kt = 0; kt < 8; ++kt) {
            const int vrow = kt * 16 + (lane & 15);
            #pragma unroll
            for (int vc = 0; vc < 4; ++vc) {
                int c16 = vc * 2 + (lane >> 4);
                uint32_t voff = vrow * 128 + ((c16 ^ (vrow & 7)) << 4);
                uint32_t r0, r1, r2, r3;
                ldm_x4_t(r0, r1, r2, r3, vs + voff);
                mma16816(oacc[2 * vc],     phi[kt], r0, r1);
                mma16816(oacc[2 * vc + 1], phi[kt], r2, r3);
                mma16816(oacc[2 * vc],     plo[kt], r0, r1);
                mma16816(oacc[2 * vc + 1], plo[kt], r2, r3);
                ldm_x4_t(r0, r1, r2, r3, vs + 16384 + voff);
                mma16816(oacc[2 * vc],     phi[kt], r0, r1);
                mma16816(oacc[2 * vc + 1], phi[kt], r2, r3);
            }
        }
        __syncthreads();
        #pragma unroll
        for (int j = 0; j < 8; ++j) {
            int col = j * 8 + t4 * 2;
            *(float2*)&Os[(m0 + g) * 66 + col]     = make_float2(oacc[j][0], oacc[j][1]);
            *(float2*)&Os[(m0 + g + 8) * 66 + col] = make_float2(oacc[j][2], oacc[j][3]);
        }
        __syncthreads();
        #pragma unroll
        for (int it = 0; it < 32; ++it) {
            int idx = it * 256 + tid;
            int c = idx >> 7, w = idx & 127;
            size_t gaddr = (((size_t)b * 256 + cc * 64 + c) * 128 + h) * 128 + w;
            out[gaddr] = a[gaddr] + Os[w * 66 + c] * wpv;
        }
    }
}

extern "C" void kernel_launch(void* const* d_in, const int* in_sizes, int n_in,
                              void* d_out, int out_size)
{
    const float* a  = (const float*)d_in[0];
    const float* wq = (const float*)d_in[1];
    const float* bq = (const float*)d_in[2];
    const float* wk = (const float*)d_in[3];
    const float* bk = (const float*)d_in[4];
    const float* wv = (const float*)d_in[5];
    const float* bv = (const float*)d_in[6];
    const float* Wp = (const float*)d_in[7];
    float* out = (float*)d_out;
    (void)in_sizes; (void)n_in; (void)out_size;

    cudaFuncSetAttribute(qkv_mma, cudaFuncAttributeMaxDynamicSharedMemorySize, QKV_SMEM);
    cudaFuncSetAttribute(attn_mma, cudaFuncAttributeMaxDynamicSharedMemorySize, ATTN_SMEM);

    wconvert<<<768, 256>>>(wq, wk, wv);
    qkv_mma<<<dim3(6, 1024), 256, QKV_SMEM>>>(a, bq, bk, bv);
    attn_mma<<<1024, 256, ATTN_SMEM>>>(a, Wp, out);
}

// round 6
// speedup vs baseline: 1.4359x; 1.4359x over previous
#include <cuda_runtime.h>
#include <cuda_bf16.h>
#include <stdint.h>
#include <math.h>

#define B_DIM 8
#define C_DIM 256
#define H_DIM 128
#define W_DIM 128
#define HW    (H_DIM * W_DIM)
#define NTOK  (B_DIM * HW)
#define QK_SCALE 0.0625f

// q/k/v bf16 hi/lo split, [token][channel]
__device__ __nv_bfloat16 g_qhi[NTOK * C_DIM];
__device__ __nv_bfloat16 g_qlo[NTOK * C_DIM];
__device__ __nv_bfloat16 g_khi[NTOK * C_DIM];
__device__ __nv_bfloat16 g_klo[NTOK * C_DIM];
__device__ __nv_bfloat16 g_vhi[NTOK * C_DIM];
__device__ __nv_bfloat16 g_vlo[NTOK * C_DIM];
// X in c-major bf16 split: [c][token]
__device__ __nv_bfloat16 g_xhi[C_DIM * NTOK];
__device__ __nv_bfloat16 g_xlo[C_DIM * NTOK];
// Weights split: [mat][o][c]
__device__ __nv_bfloat16 g_whi[3 * C_DIM * C_DIM];
__device__ __nv_bfloat16 g_wlo[3 * C_DIM * C_DIM];

__device__ __forceinline__ uint32_t smem_u32(const void* p) {
    uint32_t a;
    asm("{ .reg .u64 t; cvta.to.shared.u64 t, %1; cvt.u32.u64 %0, t; }" : "=r"(a) : "l"(p));
    return a;
}
__device__ __forceinline__ void cp16(uint32_t dst, const void* src) {
    asm volatile("cp.async.cg.shared.global [%0], [%1], 16;" :: "r"(dst), "l"(src));
}
__device__ __forceinline__ void cp_commit() { asm volatile("cp.async.commit_group;" ::: "memory"); }
__device__ __forceinline__ void cp_wait1()  { asm volatile("cp.async.wait_group 1;" ::: "memory"); }
__device__ __forceinline__ void cp_wait0()  { asm volatile("cp.async.wait_group 0;" ::: "memory"); }

__device__ __forceinline__ void ldm_x4(uint32_t& r0, uint32_t& r1, uint32_t& r2, uint32_t& r3, uint32_t addr) {
    asm volatile("ldmatrix.sync.aligned.m8n8.x4.shared.b16 {%0,%1,%2,%3}, [%4];"
                 : "=r"(r0), "=r"(r1), "=r"(r2), "=r"(r3) : "r"(addr));
}
__device__ __forceinline__ void ldm_x4_t(uint32_t& r0, uint32_t& r1, uint32_t& r2, uint32_t& r3, uint32_t addr) {
    asm volatile("ldmatrix.sync.aligned.m8n8.x4.trans.shared.b16 {%0,%1,%2,%3}, [%4];"
                 : "=r"(r0), "=r"(r1), "=r"(r2), "=r"(r3) : "r"(addr));
}
__device__ __forceinline__ void mma16816(float* c, const uint32_t* a, uint32_t b0, uint32_t b1) {
    asm volatile("mma.sync.aligned.m16n8k16.row.col.f32.bf16.bf16.f32 "
                 "{%0,%1,%2,%3},{%4,%5,%6,%7},{%8,%9},{%0,%1,%2,%3};"
                 : "+f"(c[0]), "+f"(c[1]), "+f"(c[2]), "+f"(c[3])
                 : "r"(a[0]), "r"(a[1]), "r"(a[2]), "r"(a[3]), "r"(b0), "r"(b1));
}
__device__ __forceinline__ void mma16816v(float& c0, float& c1, float& c2, float& c3,
                                          uint32_t a0, uint32_t a1, uint32_t a2, uint32_t a3,
                                          uint32_t b0, uint32_t b1) {
    asm volatile("mma.sync.aligned.m16n8k16.row.col.f32.bf16.bf16.f32 "
                 "{%0,%1,%2,%3},{%4,%5,%6,%7},{%8,%9},{%0,%1,%2,%3};"
                 : "+f"(c0), "+f"(c1), "+f"(c2), "+f"(c3)
                 : "r"(a0), "r"(a1), "r"(a2), "r"(a3), "r"(b0), "r"(b1));
}
__device__ __forceinline__ uint32_t pk_hi(float x, float y) {
    __nv_bfloat162 t = __floats2bfloat162_rn(x, y);
    return *(uint32_t*)&t;
}
__device__ __forceinline__ uint32_t pk_lo(float x, float y) {
    float xh = __bfloat162float(__float2bfloat16(x));
    float yh = __bfloat162float(__float2bfloat16(y));
    __nv_bfloat162 t = __floats2bfloat162_rn(x - xh, y - yh);
    return *(uint32_t*)&t;
}

__global__ __launch_bounds__(256)
void wconvert(const float* __restrict__ wq, const float* __restrict__ wk,
              const float* __restrict__ wv)
{
    int idx = blockIdx.x * 256 + threadIdx.x;
    int mat = idx >> 16, r = idx & 65535;
    const float* src = (mat == 0) ? wq : (mat == 1) ? wk : wv;
    float v = src[r];
    __nv_bfloat16 hi = __float2bfloat16(v);
    g_whi[idx] = hi;
    g_wlo[idx] = __float2bfloat16(v - __bfloat162float(hi));
}

// Coalesced X conversion: a NCHW fp32 -> c-major [c][token] bf16 hi/lo
__global__ __launch_bounds__(256)
void xconvert(const float* __restrict__ a)
{
    int idx4 = blockIdx.x * 256 + threadIdx.x;
    int b    = idx4 >> 20;
    int rem  = idx4 & 1048575;
    int c    = rem >> 12;
    int hw4  = rem & 4095;
    float4 v = *(const float4*)(a + (size_t)idx4 * 4);
    size_t o = (size_t)c * NTOK + (size_t)b * HW + (size_t)hw4 * 4;
    float hx = __bfloat162float(__float2bfloat16(v.x));
    float hy = __bfloat162float(__float2bfloat16(v.y));
    float hz = __bfloat162float(__float2bfloat16(v.z));
    float hw = __bfloat162float(__float2bfloat16(v.w));
    __nv_bfloat162* ph = (__nv_bfloat162*)(g_xhi + o);
    ph[0] = __floats2bfloat162_rn(v.x, v.y);
    ph[1] = __floats2bfloat162_rn(v.z, v.w);
    __nv_bfloat162* pl = (__nv_bfloat162*)(g_xlo + o);
    pl[0] = __floats2bfloat162_rn(v.x - hx, v.y - hy);
    pl[1] = __floats2bfloat162_rn(v.z - hz, v.w - hw);
}

// ===========================================================================
// QKV GEMM (R3 structure, 64KB smem, 2 CTAs/SM). Epilogue emits bf16 hi/lo.
// ===========================================================================
#define QKV_SMEM 65536

__device__ __forceinline__ void load_tileA(uint32_t dstBase, const __nv_bfloat16* src, int tid)
{
    #pragma unroll
    for (int it = 0; it < 4; ++it) {
        int id = it * 256 + tid;
        int row = id >> 4, c16 = id & 15;
        cp16(dstBase + row * 256 + ((c16 ^ (row & 7)) << 4),
             src + (size_t)row * NTOK + c16 * 8);
    }
}
__device__ __forceinline__ void load_tileB(uint32_t dstBase, const __nv_bfloat16* src, int tid)
{
    #pragma unroll
    for (int it = 0; it < 4; ++it) {
        int id = it * 256 + tid;
        int row = id >> 3, c16 = id & 7;
        cp16(dstBase + row * 128 + ((c16 ^ (row & 7)) << 4),
             src + row * 256 + c16 * 8);
    }
}

__global__ __launch_bounds__(256, 2)
void qkv_mma(const float* __restrict__ bq, const float* __restrict__ bk,
             const float* __restrict__ bv)
{
    extern __shared__ char smem[];
    const uint32_t sb = smem_u32(smem);
    const int tid = threadIdx.x, lane = tid & 31, wid = tid >> 5;
    const int wm0 = (wid & 3) * 32;
    const int wn0 = (wid >> 2) * 64;
    const int mat  = blockIdx.x >> 1;
    const int half = blockIdx.x & 1;
    const int tok0 = blockIdx.y * 128;

    float acc[2][8][4];
    #pragma unroll
    for (int mt = 0; mt < 2; ++mt)
        #pragma unroll
        for (int n8 = 0; n8 < 8; ++n8)
            #pragma unroll
            for (int e = 0; e < 4; ++e) acc[mt][n8][e] = 0.0f;

    auto srcA = [&](int c) -> const __nv_bfloat16* {
        int seg = c >> 2, kin = (c & 3) * 64;
        const __nv_bfloat16* x = (seg < 2) ? g_xhi : g_xlo;
        return x + (size_t)kin * NTOK + tok0;
    };
    auto srcB = [&](int c) -> const __nv_bfloat16* {
        int seg = c >> 2, kin = (c & 3) * 64;
        const __nv_bfloat16* w = (seg == 1) ? g_wlo : g_whi;
        return w + mat * 65536 + half * 32768 + kin;
    };

    load_tileA(sb, srcA(0), tid);
    load_tileB(sb + 16384, srcB(0), tid);
    cp_commit();

    for (int c = 0; c < 12; ++c) {
        if (c + 1 < 12) {
            uint32_t st = sb + ((c + 1) & 1) * 32768;
            load_tileA(st, srcA(c + 1), tid);
            load_tileB(st + 16384, srcB(c + 1), tid);
            cp_commit();
            cp_wait1();
        } else cp_wait0();
        __syncthreads();

        const uint32_t Ab = sb + (c & 1) * 32768;
        const uint32_t Bb = Ab + 16384;

        #pragma unroll
        for (int ks = 0; ks < 4; ++ks) {
            uint32_t af[2][4];
            {
                const int arow = ks * 16 + (lane & 7) + ((lane >> 4) << 3);
                #pragma unroll
                for (int mt = 0; mt < 2; ++mt) {
                    int chunk = (wm0 >> 3) + mt * 2 + ((lane >> 3) & 1);
                    uint32_t addr = Ab + arow * 256 + ((chunk ^ (arow & 7)) << 4);
                    ldm_x4_t(af[mt][0], af[mt][1], af[mt][2], af[mt][3], addr);
                }
            }
            uint32_t bf[4][4];
            {
                const int rbase = (lane & 7) + ((lane >> 3) & 1) * 8;
                const int c16 = ks * 2 + (lane >> 4);
                #pragma unroll
                for (int ng = 0; ng < 4; ++ng) {
                    int brow = wn0 + ng * 16 + rbase;
                    uint32_t addr = Bb + brow * 128 + ((c16 ^ (brow & 7)) << 4);
                    ldm_x4(bf[ng][0], bf[ng][1], bf[ng][2], bf[ng][3], addr);
                }
            }
            #pragma unroll
            for (int mt = 0; mt < 2; ++mt)
                #pragma unroll
                for (int n8 = 0; n8 < 8; ++n8) {
                    int gg = n8 >> 1, p = n8 & 1;
                    mma16816v(acc[mt][n8][0], acc[mt][n8][1], acc[mt][n8][2], acc[mt][n8][3],
                              af[mt][0], af[mt][1], af[mt][2], af[mt][3],
                              bf[gg][p], bf[gg][p + 2]);
                }
        }
        __syncthreads();
    }

    const float* bias = (mat == 0) ? bq : (mat == 1) ? bk : bv;
    const float scale = (mat == 0) ? QK_SCALE : 1.0f;
    __nv_bfloat16* dhi = (mat == 0) ? g_qhi : (mat == 1) ? g_khi : g_vhi;
    __nv_bfloat16* dlo = (mat == 0) ? g_qlo : (mat == 1) ? g_klo : g_vlo;

    const int g = lane >> 2, t = lane & 3;
    #pragma unroll
    for (int mt = 0; mt < 2; ++mt) {
        size_t r0 = (size_t)(tok0 + wm0 + mt * 16 + g), r1 = r0 + 8;
        #pragma unroll
        for (int n8 = 0; n8 < 8; ++n8) {
            int o = half * 128 + wn0 + n8 * 8 + t * 2;
            float b0v = bias[o], b1v = bias[o + 1];
            float v00 = (acc[mt][n8][0] + b0v) * scale;
            float v01 = (acc[mt][n8][1] + b1v) * scale;
            float v10 = (acc[mt][n8][2] + b0v) * scale;
            float v11 = (acc[mt][n8][3] + b1v) * scale;
            *(uint32_t*)(dhi + r0 * 256 + o) = pk_hi(v00, v01);
            *(uint32_t*)(dlo + r0 * 256 + o) = pk_lo(v00, v01);
            *(uint32_t*)(dhi + r1 * 256 + o) = pk_hi(v10, v11);
            *(uint32_t*)(dlo + r1 * 256 + o) = pk_lo(v10, v11);
        }
    }
}

// ===========================================================================
// HMMA attention (unchanged from R5; passed there)
// ===========================================================================
#define ATTN_SMEM 164864

__global__ __launch_bounds__(256)
void attn_mma(const float* __restrict__ a, const float* __restrict__ Wp,
              float* __restrict__ out)
{
    extern __shared__ char smem[];
    const uint32_t sb = smem_u32(smem);
    float* Os = (float*)(smem + 131072);
    const int tid = threadIdx.x, lane = tid & 31, wid = tid >> 5;
    const int m0 = wid * 16;
    const int bh = blockIdx.x, b = bh >> 7, h = bh & 127;
    const size_t tokbase = (size_t)bh * 128;

    auto loadQK = [&](int stg, int kc) {
        uint32_t st = sb + stg * 65536;
        const size_t scol = tokbase * 256 + kc * 64;
        #pragma unroll
        for (int it = 0; it < 4; ++it) {
            int id = it * 256 + tid;
            int row = id >> 3, c16 = id & 7;
            uint32_t doff = row * 128 + ((c16 ^ (row & 7)) << 4);
            size_t soff = scol + (size_t)row * 256 + c16 * 8;
            cp16(st + 0     + doff, g_qhi + soff);
            cp16(st + 16384 + doff, g_qlo + soff);
            cp16(st + 32768 + doff, g_khi + soff);
            cp16(st + 49152 + doff, g_klo + soff);
        }
    };
    auto loadV = [&](int stg, int cc) {
        uint32_t st = sb + stg * 32768;
        const size_t scol = tokbase * 256 + cc * 64;
        #pragma unroll
        for (int it = 0; it < 4; ++it) {
            int id = it * 256 + tid;
            int row = id >> 3, c16 = id & 7;
            uint32_t doff = row * 128 + ((c16 ^ (row & 7)) << 4);
            size_t soff = scol + (size_t)row * 256 + c16 * 8;
            cp16(st + 0     + doff, g_vhi + soff);
            cp16(st + 16384 + doff, g_vlo + soff);
        }
    };

    float sacc[16][4];
    #pragma unroll
    for (int j = 0; j < 16; ++j)
        #pragma unroll
        for (int e = 0; e < 4; ++e) sacc[j][e] = 0.0f;

    loadQK(0, 0); cp_commit();
    for (int kc = 0; kc < 4; ++kc) {
        if (kc < 3) { loadQK((kc + 1) & 1, kc + 1); cp_commit(); cp_wait1(); }
        else cp_wait0();
        __syncthreads();
        const uint32_t st = sb + (kc & 1) * 65536;
        #pragma unroll
        for (int ks = 0; ks < 4; ++ks) {
            uint32_t ah[4], al[4];
            const int c16 = ks * 2 + (lane >> 4);
            int arow = m0 + (lane & 15);
            uint32_t aoff = arow * 128 + ((c16 ^ (arow & 7)) << 4);
            ldm_x4(ah[0], ah[1], ah[2], ah[3], st + aoff);
            ldm_x4(al[0], al[1], al[2], al[3], st + 16384 + aoff);
            #pragma unroll
            for (int bn = 0; bn < 8; ++bn) {
                int brow = bn * 16 + (lane & 15);
                uint32_t boff = brow * 128 + ((c16 ^ (brow & 7)) << 4);
                uint32_t b0, b1, b2, b3;
                ldm_x4(b0, b1, b2, b3, st + 32768 + boff);
                mma16816(sacc[2 * bn],     ah, b0, b2);
                mma16816(sacc[2 * bn + 1], ah, b1, b3);
                mma16816(sacc[2 * bn],     al, b0, b2);
                mma16816(sacc[2 * bn + 1], al, b1, b3);
                ldm_x4(b0, b1, b2, b3, st + 49152 + boff);
                mma16816(sacc[2 * bn],     ah, b0, b2);
                mma16816(sacc[2 * bn + 1], ah, b1, b3);
            }
        }
        __syncthreads();
    }
    loadV(0, 0); cp_commit();

    float mx0 = -1e30f, mx1 = -1e30f;
    #pragma unroll
    for (int j = 0; j < 16; ++j) {
        mx0 = fmaxf(mx0, fmaxf(sacc[j][0], sacc[j][1]));
        mx1 = fmaxf(mx1, fmaxf(sacc[j][2], sacc[j][3]));
    }
    mx0 = fmaxf(mx0, __shfl_xor_sync(~0u, mx0, 1));
    mx0 = fmaxf(mx0, __shfl_xor_sync(~0u, mx0, 2));
    mx1 = fmaxf(mx1, __shfl_xor_sync(~0u, mx1, 1));
    mx1 = fmaxf(mx1, __shfl_xor_sync(~0u, mx1, 2));
    float sum0 = 0.0f, sum1 = 0.0f;
    #pragma unroll
    for (int j = 0; j < 16; ++j) {
        sacc[j][0] = __expf(sacc[j][0] - mx0); sum0 += sacc[j][0];
        sacc[j][1] = __expf(sacc[j][1] - mx0); sum0 += sacc[j][1];
        sacc[j][2] = __expf(sacc[j][2] - mx1); sum1 += sacc[j][2];
        sacc[j][3] = __expf(sacc[j][3] - mx1); sum1 += sacc[j][3];
    }
    sum0 += __shfl_xor_sync(~0u, sum0, 1);
    sum0 += __shfl_xor_sync(~0u, sum0, 2);
    sum1 += __shfl_xor_sync(~0u, sum1, 1);
    sum1 += __shfl_xor_sync(~0u, sum1, 2);
    const float inv0 = 1.0f / sum0, inv1 = 1.0f / sum1;

    uint32_t phi[8][4], plo[8][4];
    #pragma unroll
    for (int kt = 0; kt < 8; ++kt) {
        int j0 = 2 * kt, j1 = 2 * kt + 1;
        float v00 = sacc[j0][0] * inv0, v01 = sacc[j0][1] * inv0;
        float v02 = sacc[j0][2] * inv1, v03 = sacc[j0][3] * inv1;
        float v10 = sacc[j1][0] * inv0, v11 = sacc[j1][1] * inv0;
        float v12 = sacc[j1][2] * inv1, v13 = sacc[j1][3] * inv1;
        phi[kt][0] = pk_hi(v00, v01); plo[kt][0] = pk_lo(v00, v01);
        phi[kt][1] = pk_hi(v02, v03); plo[kt][1] = pk_lo(v02, v03);
        phi[kt][2] = pk_hi(v10, v11); plo[kt][2] = pk_lo(v10, v11);
        phi[kt][3] = pk_hi(v12, v13); plo[kt][3] = pk_lo(v12, v13);
    }

    const float wpv = Wp[0];
    const int g = lane >> 2, t4 = lane & 3;

    for (int cc = 0; cc < 4; ++cc) {
        if (cc < 3) { loadV((cc + 1) & 1, cc + 1); cp_commit(); cp_wait1(); }
        else cp_wait0();
        __syncthreads();
        const uint32_t vs = sb + (cc & 1) * 32768;
        float oacc[8][4];
        #pragma unroll
        for (int j = 0; j < 8; ++j)
            #pragma unroll
            for (int e = 0; e < 4; ++e) oacc[j][e] = 0.0f;

        #pragma unroll
        for (int kt = 0; kt < 8; ++kt) {
            const int vrow = kt * 16 + (lane & 15);
            #pragma unroll
            for (int vc = 0; vc < 4; ++vc) {
                int c16 = vc * 2 + (lane >> 4);
                uint32_t voff = vrow * 128 + ((c16 ^ (vrow & 7)) << 4);
                uint32_t r0, r1, r2, r3;
                ldm_x4_t(r0, r1, r2, r3, vs + voff);
                mma16816(oacc[2 * vc],     phi[kt], r0, r1);
                mma16816(oacc[2 * vc + 1], phi[kt], r2, r3);
                mma16816(oacc[2 * vc],     plo[kt], r0, r1);
                mma16816(oacc[2 * vc + 1], plo[kt], r2, r3);
                ldm_x4_t(r0, r1, r2, r3, vs + 16384 + voff);
                mma16816(oacc[2 * vc],     phi[kt], r0, r1);
                mma16816(oacc[2 * vc + 1], phi[kt], r2, r3);
            }
        }
        __syncthreads();
        #pragma unroll
        for (int j = 0; j < 8; ++j) {
            int col = j * 8 + t4 * 2;
            *(float2*)&Os[(m0 + g) * 66 + col]     = make_float2(oacc[j][0], oacc[j][1]);
            *(float2*)&Os[(m0 + g + 8) * 66 + col] = make_float2(oacc[j][2], oacc[j][3]);
        }
        __syncthreads();
        #pragma unroll
        for (int it = 0; it < 32; ++it) {
            int idx = it * 256 + tid;
            int c = idx >> 7, w = idx & 127;
            size_t gaddr = (((size_t)b * 256 + cc * 64 + c) * 128 + h) * 128 + w;
            out[gaddr] = a[gaddr] + Os[w * 66 + c] * wpv;
        }
    }
}

extern "C" void kernel_launch(void* const* d_in, const int* in_sizes, int n_in,
                              void* d_out, int out_size)
{
    const float* a  = (const float*)d_in[0];
    const float* wq = (const float*)d_in[1];
    const float* bq = (const float*)d_in[2];
    const float* wk = (const float*)d_in[3];
    const float* bk = (const float*)d_in[4];
    const float* wv = (const float*)d_in[5];
    const float* bv = (const float*)d_in[6];
    const float* Wp = (const float*)d_in[7];
    float* out = (float*)d_out;
    (void)in_sizes; (void)n_in; (void)out_size;

    cudaFuncSetAttribute(qkv_mma, cudaFuncAttributeMaxDynamicSharedMemorySize, QKV_SMEM);
    cudaFuncSetAttribute(attn_mma, cudaFuncAttributeMaxDynamicSharedMemorySize, ATTN_SMEM);

    wconvert<<<768, 256>>>(wq, wk, wv);
    xconvert<<<32768, 256>>>(a);
    qkv_mma<<<dim3(6, 1024), 256, QKV_SMEM>>>(bq, bk, bv);
    attn_mma<<<1024, 256, ATTN_SMEM>>>(a, Wp, out);
}